// round 1
// baseline (speedup 1.0000x reference)
#include <cuda_runtime.h>

// Shapes (fixed by the problem)
#define BDIM 2
#define CCH  64
#define DD   32
#define HWN  4096
#define NLOC (BDIM*DD*HWN)    // 262144 spatial locations
#define NU   (BDIM*HWN*8)     // 65536 attention units (b, hw, head)
#define NEL  16777216         // B*C*D*H*W

typedef unsigned long long u64;

// Scratch: q/k/v/ctx in attention-friendly layout [unit][d][e] (unit=(b*HW+s)*8+head)
__device__ __align__(16) float g_q[NEL];
__device__ __align__(16) float g_k[NEL];
__device__ __align__(16) float g_v[NEL];
__device__ __align__(16) float g_c[NEL];

__device__ __forceinline__ u64 pk2(float lo, float hi) {
    u64 r; asm("mov.b64 %0, {%1,%2};" : "=l"(r) : "f"(lo), "f"(hi)); return r;
}
__device__ __forceinline__ float2 upk2(u64 v) {
    float2 r; asm("mov.b64 {%0,%1}, %2;" : "=f"(r.x), "=f"(r.y) : "l"(v)); return r;
}
// Packed dual-FMA: d = a*b + d (elementwise on f32x2)
#define FMA2(d, a, b) asm("fma.rn.f32x2 %0, %1, %2, %0;" : "+l"(d) : "l"(a), "l"(b))

// ---------------------------------------------------------------------------
// Kernel 1: Q projection. One thread per (b,d,s). x channel vector in regs
// (packed f32x2), weight rows broadcast from shared. Output to g_q[u][d][e].
// ---------------------------------------------------------------------------
__global__ void __launch_bounds__(256) k_proj_q(const float* __restrict__ x,
                                                const float* __restrict__ Wg)
{
    __shared__ __align__(16) float sW[4096];
    #pragma unroll
    for (int i = 0; i < 16; i++) sW[threadIdx.x + i*256] = Wg[threadIdx.x + i*256];
    __syncthreads();

    int t = blockIdx.x*256 + threadIdx.x;
    int s = t & (HWN-1);
    int d = (t >> 12) & 31;
    int b = t >> 17;

    const float* xp = x + b*8388608 + d*4096 + s;   // channel stride 131072
    u64 xv[32];
    #pragma unroll
    for (int c2 = 0; c2 < 32; c2++)
        xv[c2] = pk2(xp[(2*c2)*131072], xp[(2*c2+1)*131072]);

    int base = (b*HWN + s)*2048 + d*8;              // (u_base)*256 + d*8
    #pragma unroll 1
    for (int head = 0; head < 8; head++) {
        float q8[8];
        #pragma unroll
        for (int e = 0; e < 8; e++) {
            const ulonglong2* wp = (const ulonglong2*)&sW[(head*8 + e)*64];
            u64 a0 = 0ull, a1 = 0ull;
            #pragma unroll
            for (int j = 0; j < 16; j++) {
                ulonglong2 w = wp[j];
                FMA2(a0, w.x, xv[2*j]);
                FMA2(a1, w.y, xv[2*j+1]);
            }
            float2 f0 = upk2(a0), f1 = upk2(a1);
            q8[e] = (f0.x + f0.y) + (f1.x + f1.y);
        }
        float4* dst = (float4*)(g_q + base + head*256);
        dst[0] = make_float4(q8[0], q8[1], q8[2], q8[3]);
        dst[1] = make_float4(q8[4], q8[5], q8[6], q8[7]);
    }
}

// ---------------------------------------------------------------------------
// Kernel 2: fused K+V projection (reads key_feats once).
// ---------------------------------------------------------------------------
__global__ void __launch_bounds__(256) k_proj_kv(const float* __restrict__ x,
                                                 const float* __restrict__ Wkg,
                                                 const float* __restrict__ Wvg)
{
    __shared__ __align__(16) float sWk[4096];
    __shared__ __align__(16) float sWv[4096];
    #pragma unroll
    for (int i = 0; i < 16; i++) {
        sWk[threadIdx.x + i*256] = Wkg[threadIdx.x + i*256];
        sWv[threadIdx.x + i*256] = Wvg[threadIdx.x + i*256];
    }
    __syncthreads();

    int t = blockIdx.x*256 + threadIdx.x;
    int s = t & (HWN-1);
    int d = (t >> 12) & 31;
    int b = t >> 17;

    const float* xp = x + b*8388608 + d*4096 + s;
    u64 xv[32];
    #pragma unroll
    for (int c2 = 0; c2 < 32; c2++)
        xv[c2] = pk2(xp[(2*c2)*131072], xp[(2*c2+1)*131072]);

    int base = (b*HWN + s)*2048 + d*8;
    #pragma unroll 1
    for (int head = 0; head < 8; head++) {
        float k8[8], v8[8];
        #pragma unroll
        for (int e = 0; e < 8; e++) {
            const ulonglong2* wkp = (const ulonglong2*)&sWk[(head*8 + e)*64];
            const ulonglong2* wvp = (const ulonglong2*)&sWv[(head*8 + e)*64];
            u64 ak0 = 0ull, ak1 = 0ull, av0 = 0ull, av1 = 0ull;
            #pragma unroll
            for (int j = 0; j < 16; j++) {
                ulonglong2 wk = wkp[j];
                ulonglong2 wv = wvp[j];
                FMA2(ak0, wk.x, xv[2*j]);
                FMA2(ak1, wk.y, xv[2*j+1]);
                FMA2(av0, wv.x, xv[2*j]);
                FMA2(av1, wv.y, xv[2*j+1]);
            }
            float2 fk0 = upk2(ak0), fk1 = upk2(ak1);
            float2 fv0 = upk2(av0), fv1 = upk2(av1);
            k8[e] = (fk0.x + fk0.y) + (fk1.x + fk1.y);
            v8[e] = (fv0.x + fv0.y) + (fv1.x + fv1.y);
        }
        float4* dk = (float4*)(g_k + base + head*256);
        dk[0] = make_float4(k8[0], k8[1], k8[2], k8[3]);
        dk[1] = make_float4(k8[4], k8[5], k8[6], k8[7]);
        float4* dv = (float4*)(g_v + base + head*256);
        dv[0] = make_float4(v8[0], v8[1], v8[2], v8[3]);
        dv[1] = make_float4(v8[4], v8[5], v8[6], v8[7]);
    }
}

// ---------------------------------------------------------------------------
// Kernel 3: attention. One warp per unit u=(b,hw,head); lane = d row.
// q row in packed regs, K/V tiles staged to shared (broadcast reads).
// sim[d][d'] = dot8(q[d], k[d']) * 8^-0.5; softmax over d'; ctx = p @ V.
// ---------------------------------------------------------------------------
__global__ void __launch_bounds__(256) k_attn()
{
    __shared__ __align__(16) float ks[8][256];
    __shared__ __align__(16) float vs[8][256];
    int warp = threadIdx.x >> 5, lane = threadIdx.x & 31;
    int u = blockIdx.x*8 + warp;

    const float4* kp = (const float4*)(g_k + u*256);
    const float4* vp = (const float4*)(g_v + u*256);
    float4* ksw = (float4*)ks[warp];
    float4* vsw = (float4*)vs[warp];
    ksw[lane*2]     = kp[lane*2];
    ksw[lane*2 + 1] = kp[lane*2 + 1];
    vsw[lane*2]     = vp[lane*2];
    vsw[lane*2 + 1] = vp[lane*2 + 1];

    const float4* qp = (const float4*)(g_q + u*256 + lane*8);
    float4 q0 = qp[0], q1 = qp[1];
    u64 qv0 = pk2(q0.x, q0.y), qv1 = pk2(q0.z, q0.w);
    u64 qv2 = pk2(q1.x, q1.y), qv3 = pk2(q1.z, q1.w);
    __syncwarp();

    float sim[32];
    #pragma unroll
    for (int j = 0; j < 32; j++) {
        const ulonglong2* kq = (const ulonglong2*)&ks[warp][j*8];
        ulonglong2 ka = kq[0], kb = kq[1];
        u64 a0 = 0ull, a1 = 0ull;
        FMA2(a0, ka.x, qv0); FMA2(a1, ka.y, qv1);
        FMA2(a0, kb.x, qv2); FMA2(a1, kb.y, qv3);
        float2 f0 = upk2(a0), f1 = upk2(a1);
        sim[j] = ((f0.x + f0.y) + (f1.x + f1.y)) * 0.35355339059327373f;
    }

    float m = sim[0];
    #pragma unroll
    for (int j = 1; j < 32; j++) m = fmaxf(m, sim[j]);

    float ssum = 0.f;
    u64 c0 = 0ull, c1 = 0ull, c2 = 0ull, c3 = 0ull;
    #pragma unroll
    for (int j = 0; j < 32; j++) {
        float p = __expf(sim[j] - m);
        ssum += p;
        u64 pp = pk2(p, p);
        const ulonglong2* vq = (const ulonglong2*)&vs[warp][j*8];
        ulonglong2 va = vq[0], vb = vq[1];
        FMA2(c0, va.x, pp); FMA2(c1, va.y, pp);
        FMA2(c2, vb.x, pp); FMA2(c3, vb.y, pp);
    }

    float inv = 1.f / ssum;
    float2 r0 = upk2(c0), r1 = upk2(c1), r2 = upk2(c2), r3 = upk2(c3);
    float4* dst = (float4*)(g_c + u*256 + lane*8);
    dst[0] = make_float4(r0.x*inv, r0.y*inv, r1.x*inv, r1.y*inv);
    dst[1] = make_float4(r2.x*inv, r2.y*inv, r3.x*inv, r3.y*inv);
}

// ---------------------------------------------------------------------------
// Kernel 4: output projection. Gathers ctx channel vector (8 heads x 2 float4,
// sector-full), GEMV with Wo, coalesced writes to [B,C,D,H,W].
// ---------------------------------------------------------------------------
__global__ void __launch_bounds__(256) k_proj_o(const float* __restrict__ Wg,
                                                float* __restrict__ out)
{
    __shared__ __align__(16) float sW[4096];
    #pragma unroll
    for (int i = 0; i < 16; i++) sW[threadIdx.x + i*256] = Wg[threadIdx.x + i*256];
    __syncthreads();

    int t = blockIdx.x*256 + threadIdx.x;
    int s = t & (HWN-1);
    int d = (t >> 12) & 31;
    int b = t >> 17;

    const float4* cp = (const float4*)(g_c + (b*HWN + s)*2048 + d*8);
    u64 xv[32];
    #pragma unroll
    for (int head = 0; head < 8; head++) {
        float4 u0 = cp[head*64];
        float4 u1 = cp[head*64 + 1];
        xv[head*4 + 0] = pk2(u0.x, u0.y);
        xv[head*4 + 1] = pk2(u0.z, u0.w);
        xv[head*4 + 2] = pk2(u1.x, u1.y);
        xv[head*4 + 3] = pk2(u1.z, u1.w);
    }

    int obase = b*8388608 + d*4096 + s;
    #pragma unroll 1
    for (int og = 0; og < 8; og++) {
        float y8[8];
        #pragma unroll
        for (int e = 0; e < 8; e++) {
            const ulonglong2* wp = (const ulonglong2*)&sW[(og*8 + e)*64];
            u64 a0 = 0ull, a1 = 0ull;
            #pragma unroll
            for (int j = 0; j < 16; j++) {
                ulonglong2 w = wp[j];
                FMA2(a0, w.x, xv[2*j]);
                FMA2(a1, w.y, xv[2*j+1]);
            }
            float2 f0 = upk2(a0), f1 = upk2(a1);
            y8[e] = (f0.x + f0.y) + (f1.x + f1.y);
        }
        #pragma unroll
        for (int e = 0; e < 8; e++)
            out[obase + (og*8 + e)*131072] = y8[e];
    }
}

extern "C" void kernel_launch(void* const* d_in, const int* in_sizes, int n_in,
                              void* d_out, int out_size)
{
    const float* qf = (const float*)d_in[0];
    const float* kf = (const float*)d_in[1];
    const float* Wq = (const float*)d_in[2];
    const float* Wk = (const float*)d_in[3];
    const float* Wv = (const float*)d_in[4];
    const float* Wo = (const float*)d_in[5];
    float* out = (float*)d_out;

    k_proj_q <<<NLOC/256, 256>>>(qf, Wq);
    k_proj_kv<<<NLOC/256, 256>>>(kf, Wk, Wv);
    k_attn   <<<NU/8,     256>>>();
    k_proj_o <<<NLOC/256, 256>>>(Wo, out);
}

// round 3
// speedup vs baseline: 1.2821x; 1.2821x over previous
#include <cuda_runtime.h>

#define NEL 16777216   // B*C*D*H*W
typedef unsigned long long u64;

// Scratch. q/k/v in attention layout [unit][d][e], ctx in x-layout [B][C][N].
__device__ __align__(16) float g_q[NEL];
__device__ __align__(16) float g_k[NEL];
__device__ __align__(16) float g_v[NEL];
__device__ __align__(16) float g_c[NEL];

__device__ __forceinline__ u64 pk2(float lo, float hi) {
    u64 r; asm("mov.b64 %0, {%1,%2};" : "=l"(r) : "f"(lo), "f"(hi)); return r;
}
__device__ __forceinline__ float2 upk2(u64 v) {
    float2 r; asm("mov.b64 {%0,%1}, %2;" : "=f"(r.x), "=f"(r.y) : "l"(v)); return r;
}
#define FMA2(d, a, b) asm("fma.rn.f32x2 %0, %1, %2, %0;" : "+l"(d) : "l"(a), "l"(b))

// ---------------------------------------------------------------------------
// GEMM staging helpers (proper functions — no macro token capture).
// Wt[k][o] = W[o][k] transposed to shared. xs[k][n] = 128-wide slab of x.
// ---------------------------------------------------------------------------
__device__ __forceinline__ void stage_W(float* Wt, const float* __restrict__ Wsrc) {
    for (int idx = threadIdx.x; idx < 4096; idx += 256) {
        int kk = idx >> 6, oo = idx & 63;
        Wt[kk*64 + oo] = Wsrc[oo*64 + kk];
    }
}

__device__ __forceinline__ void stage_X(float* xs, const float* __restrict__ xsrc,
                                        int b, int n0) {
    const float4* xg = (const float4*)(xsrc + b*8388608 + n0);
    float4* xs4 = (float4*)xs;
    #pragma unroll
    for (int i = 0; i < 8; i++) {
        int idx = threadIdx.x + i*256;
        int c = idx >> 5, n4 = idx & 31;
        xs4[c*32 + n4] = xg[c*32768 + n4];
    }
}

// ---------------------------------------------------------------------------
// Kernel 1: Q projection -> attention layout [unit][d][e].
// Block: [64 o x 128 n], K=64. Thread: 8 o (one head) x 4 n, acc packed f32x2.
// ---------------------------------------------------------------------------
__global__ void __launch_bounds__(256) k_proj_q(const float* __restrict__ x,
                                                const float* __restrict__ W)
{
    __shared__ __align__(16) float xs[64*128];
    __shared__ __align__(16) float Wt[64*64];
    int b = blockIdx.x >> 10;
    int n0 = (blockIdx.x & 1023) << 7;
    stage_W(Wt, W);
    stage_X(xs, x, b, n0);
    __syncthreads();

    int ot = threadIdx.x & 7, nt = threadIdx.x >> 3;
    u64 acc[4][4] = {};
    #pragma unroll 8
    for (int k = 0; k < 64; k++) {
        const ulonglong2* wp = (const ulonglong2*)&Wt[k*64 + ot*8];
        ulonglong2 wa = wp[0], wb = wp[1];
        u64 w[4] = {wa.x, wa.y, wb.x, wb.y};
        float4 xv = *(const float4*)&xs[k*128 + nt*4];
        u64 xq[4] = {pk2(xv.x,xv.x), pk2(xv.y,xv.y), pk2(xv.z,xv.z), pk2(xv.w,xv.w)};
        #pragma unroll
        for (int p = 0; p < 4; p++)
            #pragma unroll
            for (int n = 0; n < 4; n++)
                FMA2(acc[p][n], w[p], xq[n]);
    }

    int d = n0 >> 12;
    int sbase = (n0 & 4095) + nt*4;
    #pragma unroll
    for (int n = 0; n < 4; n++) {
        float2 a0 = upk2(acc[0][n]), a1 = upk2(acc[1][n]);
        float2 a2 = upk2(acc[2][n]), a3 = upk2(acc[3][n]);
        float* o = g_q + b*8388608 + (sbase + n)*2048 + ot*256 + d*8;
        ((float4*)o)[0] = make_float4(a0.x, a0.y, a1.x, a1.y);
        ((float4*)o)[1] = make_float4(a2.x, a2.y, a3.x, a3.y);
    }
}

// ---------------------------------------------------------------------------
// Kernel 2: fused K+V projection -> attention layout.
// ---------------------------------------------------------------------------
__global__ void __launch_bounds__(256) k_proj_kv(const float* __restrict__ x,
                                                 const float* __restrict__ Wk,
                                                 const float* __restrict__ Wv)
{
    __shared__ __align__(16) float xs[64*128];
    __shared__ __align__(16) float Wtk[64*64];
    __shared__ __align__(16) float Wtv[64*64];
    int b = blockIdx.x >> 10;
    int n0 = (blockIdx.x & 1023) << 7;
    stage_W(Wtk, Wk);
    stage_W(Wtv, Wv);
    stage_X(xs, x, b, n0);
    __syncthreads();

    int ot = threadIdx.x & 7, nt = threadIdx.x >> 3;
    u64 ak[4][4] = {};
    u64 av[4][4] = {};
    #pragma unroll 4
    for (int k = 0; k < 64; k++) {
        const ulonglong2* wkp = (const ulonglong2*)&Wtk[k*64 + ot*8];
        const ulonglong2* wvp = (const ulonglong2*)&Wtv[k*64 + ot*8];
        ulonglong2 wka = wkp[0], wkb = wkp[1];
        ulonglong2 wva = wvp[0], wvb = wvp[1];
        u64 wk2[4] = {wka.x, wka.y, wkb.x, wkb.y};
        u64 wv2[4] = {wva.x, wva.y, wvb.x, wvb.y};
        float4 xv = *(const float4*)&xs[k*128 + nt*4];
        u64 xq[4] = {pk2(xv.x,xv.x), pk2(xv.y,xv.y), pk2(xv.z,xv.z), pk2(xv.w,xv.w)};
        #pragma unroll
        for (int p = 0; p < 4; p++)
            #pragma unroll
            for (int n = 0; n < 4; n++) {
                FMA2(ak[p][n], wk2[p], xq[n]);
                FMA2(av[p][n], wv2[p], xq[n]);
            }
    }

    int d = n0 >> 12;
    int sbase = (n0 & 4095) + nt*4;
    #pragma unroll
    for (int n = 0; n < 4; n++) {
        int off = b*8388608 + (sbase + n)*2048 + ot*256 + d*8;
        {
            float2 a0 = upk2(ak[0][n]), a1 = upk2(ak[1][n]);
            float2 a2 = upk2(ak[2][n]), a3 = upk2(ak[3][n]);
            float* o = g_k + off;
            ((float4*)o)[0] = make_float4(a0.x, a0.y, a1.x, a1.y);
            ((float4*)o)[1] = make_float4(a2.x, a2.y, a3.x, a3.y);
        }
        {
            float2 a0 = upk2(av[0][n]), a1 = upk2(av[1][n]);
            float2 a2 = upk2(av[2][n]), a3 = upk2(av[3][n]);
            float* o = g_v + off;
            ((float4*)o)[0] = make_float4(a0.x, a0.y, a1.x, a1.y);
            ((float4*)o)[1] = make_float4(a2.x, a2.y, a3.x, a3.y);
        }
    }
}

// ---------------------------------------------------------------------------
// Kernel 3: attention. Block = (b, head, 8 consecutive s); warp per s.
// Writes ctx to g_c in x-layout [B][C][N] via shared transpose (sector-full).
// ---------------------------------------------------------------------------
__global__ void __launch_bounds__(256) k_attn()
{
    __shared__ __align__(16) float ks[8][256];
    __shared__ __align__(16) float vsm[8][256];
    __shared__ __align__(16) float sctx[8*32*9];   // [e][d][s pad 9]
    int warp = threadIdx.x >> 5, lane = threadIdx.x & 31;
    int blk = blockIdx.x;
    int s8   = blk & 511;
    int head = (blk >> 9) & 7;
    int b    = blk >> 12;
    int s = s8*8 + warp;
    int u = ((b << 12) + s)*8 + head;

    const float4* kp = (const float4*)(g_k + u*256);
    const float4* vp = (const float4*)(g_v + u*256);
    float4* ksw = (float4*)ks[warp];
    float4* vsw = (float4*)vsm[warp];
    ksw[lane*2]     = kp[lane*2];
    ksw[lane*2 + 1] = kp[lane*2 + 1];
    vsw[lane*2]     = vp[lane*2];
    vsw[lane*2 + 1] = vp[lane*2 + 1];

    const float4* qp = (const float4*)(g_q + u*256 + lane*8);
    float4 q0 = qp[0], q1 = qp[1];
    u64 qv0 = pk2(q0.x, q0.y), qv1 = pk2(q0.z, q0.w);
    u64 qv2 = pk2(q1.x, q1.y), qv3 = pk2(q1.z, q1.w);
    __syncwarp();

    float sim[32];
    #pragma unroll
    for (int j = 0; j < 32; j++) {
        const ulonglong2* kq = (const ulonglong2*)&ks[warp][j*8];
        ulonglong2 ka = kq[0], kb = kq[1];
        u64 a0 = 0ull, a1 = 0ull;
        FMA2(a0, ka.x, qv0); FMA2(a1, ka.y, qv1);
        FMA2(a0, kb.x, qv2); FMA2(a1, kb.y, qv3);
        float2 f0 = upk2(a0), f1 = upk2(a1);
        sim[j] = ((f0.x + f0.y) + (f1.x + f1.y)) * 0.35355339059327373f;
    }

    float m = sim[0];
    #pragma unroll
    for (int j = 1; j < 32; j++) m = fmaxf(m, sim[j]);

    float ssum = 0.f;
    u64 c0 = 0ull, c1 = 0ull, c2 = 0ull, c3 = 0ull;
    #pragma unroll
    for (int j = 0; j < 32; j++) {
        float p = __expf(sim[j] - m);
        ssum += p;
        u64 pp = pk2(p, p);
        const ulonglong2* vq = (const ulonglong2*)&vsm[warp][j*8];
        ulonglong2 va = vq[0], vb = vq[1];
        FMA2(c0, va.x, pp); FMA2(c1, va.y, pp);
        FMA2(c2, vb.x, pp); FMA2(c3, vb.y, pp);
    }

    float inv = 1.f / ssum;
    float2 r0 = upk2(c0), r1 = upk2(c1), r2 = upk2(c2), r3 = upk2(c3);
    float vals[8] = {r0.x*inv, r0.y*inv, r1.x*inv, r1.y*inv,
                     r2.x*inv, r2.y*inv, r3.x*inv, r3.y*inv};
    #pragma unroll
    for (int e = 0; e < 8; e++)
        sctx[e*288 + lane*9 + warp] = vals[e];
    __syncthreads();

    int e = threadIdx.x >> 5, d = threadIdx.x & 31;
    const float* sp = &sctx[e*288 + d*9];
    float4 f0 = make_float4(sp[0], sp[1], sp[2], sp[3]);
    float4 f1 = make_float4(sp[4], sp[5], sp[6], sp[7]);
    float* dst = g_c + b*8388608 + (head*8 + e)*131072 + d*4096 + s8*8;
    ((float4*)dst)[0] = f0;
    ((float4*)dst)[1] = f1;
}

// ---------------------------------------------------------------------------
// Kernel 4: O projection. Same GEMM; reads g_c (x-layout), writes out x-layout.
// ---------------------------------------------------------------------------
__global__ void __launch_bounds__(256) k_proj_o(const float* __restrict__ W,
                                                float* __restrict__ out)
{
    __shared__ __align__(16) float xs[64*128];
    __shared__ __align__(16) float Wt[64*64];
    int b = blockIdx.x >> 10;
    int n0 = (blockIdx.x & 1023) << 7;
    stage_W(Wt, W);
    stage_X(xs, g_c, b, n0);
    __syncthreads();

    int ot = threadIdx.x & 7, nt = threadIdx.x >> 3;
    u64 acc[4][4] = {};
    #pragma unroll 8
    for (int k = 0; k < 64; k++) {
        const ulonglong2* wp = (const ulonglong2*)&Wt[k*64 + ot*8];
        ulonglong2 wa = wp[0], wb = wp[1];
        u64 w[4] = {wa.x, wa.y, wb.x, wb.y};
        float4 xv = *(const float4*)&xs[k*128 + nt*4];
        u64 xq[4] = {pk2(xv.x,xv.x), pk2(xv.y,xv.y), pk2(xv.z,xv.z), pk2(xv.w,xv.w)};
        #pragma unroll
        for (int p = 0; p < 4; p++)
            #pragma unroll
            for (int n = 0; n < 4; n++)
                FMA2(acc[p][n], w[p], xq[n]);
    }

    float* ob = out + b*8388608 + n0 + nt*4;
    #pragma unroll
    for (int p = 0; p < 4; p++) {
        float2 a0 = upk2(acc[p][0]), a1 = upk2(acc[p][1]);
        float2 a2 = upk2(acc[p][2]), a3 = upk2(acc[p][3]);
        *(float4*)(ob + (ot*8 + 2*p    )*131072) = make_float4(a0.x, a1.x, a2.x, a3.x);
        *(float4*)(ob + (ot*8 + 2*p + 1)*131072) = make_float4(a0.y, a1.y, a2.y, a3.y);
    }
}

extern "C" void kernel_launch(void* const* d_in, const int* in_sizes, int n_in,
                              void* d_out, int out_size)
{
    const float* qf = (const float*)d_in[0];
    const float* kf = (const float*)d_in[1];
    const float* Wq = (const float*)d_in[2];
    const float* Wk = (const float*)d_in[3];
    const float* Wv = (const float*)d_in[4];
    const float* Wo = (const float*)d_in[5];
    float* out = (float*)d_out;

    k_proj_q <<<2048, 256>>>(qf, Wq);
    k_proj_kv<<<2048, 256>>>(kf, Wk, Wv);
    k_attn   <<<8192, 256>>>();
    k_proj_o <<<2048, 256>>>(Wo, out);
}

// round 4
// speedup vs baseline: 1.7529x; 1.3672x over previous
#include <cuda_runtime.h>

#define NEL 16777216   // B*C*D*H*W
typedef unsigned long long u64;

// Scratch. q/k/v in attention layout [b][s][head][d][e], ctx in x-layout [B][C][N].
__device__ __align__(16) float g_q[NEL];
__device__ __align__(16) float g_k[NEL];
__device__ __align__(16) float g_v[NEL];
__device__ __align__(16) float g_c[NEL];

__device__ __forceinline__ u64 pk2(float lo, float hi) {
    u64 r; asm("mov.b64 %0, {%1,%2};" : "=l"(r) : "f"(lo), "f"(hi)); return r;
}
__device__ __forceinline__ float2 upk2(u64 v) {
    float2 r; asm("mov.b64 {%0,%1}, %2;" : "=f"(r.x), "=f"(r.y) : "l"(v)); return r;
}
#define FMA2(d, a, b) asm("fma.rn.f32x2 %0, %1, %2, %0;" : "+l"(d) : "l"(a), "l"(b))

// ---------------------------------------------------------------------------
// Stage W[64][64] (row-major [o][k]) into two bank-conflict-free planes:
//   A[k*32 + ot*4 + j] = W[ot*8 + j    ][k]   (j < 4)
//   B[k*32 + ot*4 + j] = W[ot*8 + 4 + j][k]
// A float4 load at A[k*32 + ot*4] puts the 8 ot-accesses of a quarter-warp at
// 16B stride -> all 32 banks covered, conflict-free.
// ---------------------------------------------------------------------------
__device__ __forceinline__ void stage_W2(float* A, float* B,
                                         const float* __restrict__ Wsrc) {
    for (int idx = threadIdx.x; idx < 2048; idx += 128) {
        int k = idx >> 5, t = idx & 31;
        int ot = t >> 2, j = t & 3;
        A[idx] = Wsrc[(ot*8 + j)*64 + k];
        B[idx] = Wsrc[(ot*8 + 4 + j)*64 + k];
    }
}

// ---------------------------------------------------------------------------
// Kernel 1: Q projection -> attention layout.
// Block [64o x 256n], 128 threads, thread tile [8o x 16n] (acc packed over n).
// ---------------------------------------------------------------------------
__global__ void __launch_bounds__(128) k_proj_q(const float* __restrict__ x,
                                                const float* __restrict__ W)
{
    __shared__ __align__(16) float xs[64*256];
    __shared__ __align__(16) float WA[2048];
    __shared__ __align__(16) float WB[2048];
    int b = blockIdx.x >> 9;
    int n0 = (blockIdx.x & 511) << 8;
    stage_W2(WA, WB, W);
    {
        const float4* xg = (const float4*)(x + b*8388608 + n0);
        float4* xs4 = (float4*)xs;
        #pragma unroll
        for (int i = 0; i < 32; i++) {
            int idx = threadIdx.x + i*128;
            int c = idx >> 6, n4 = idx & 63;
            xs4[c*64 + n4] = xg[c*32768 + n4];
        }
    }
    __syncthreads();

    int ot = threadIdx.x & 7, nt = threadIdx.x >> 3;   // n = nt*16
    u64 acc[8][8];
    #pragma unroll
    for (int o = 0; o < 8; o++)
        #pragma unroll
        for (int np = 0; np < 8; np++) acc[o][np] = 0ull;

    #pragma unroll 2
    for (int k = 0; k < 64; k++) {
        float4 wa = *(const float4*)&WA[k*32 + ot*4];
        float4 wb = *(const float4*)&WB[k*32 + ot*4];
        u64 ws[8] = {pk2(wa.x,wa.x), pk2(wa.y,wa.y), pk2(wa.z,wa.z), pk2(wa.w,wa.w),
                     pk2(wb.x,wb.x), pk2(wb.y,wb.y), pk2(wb.z,wb.z), pk2(wb.w,wb.w)};
        const ulonglong2* xp = (const ulonglong2*)&xs[k*256 + nt*16];
        ulonglong2 x0 = xp[0], x1 = xp[1], x2 = xp[2], x3 = xp[3];
        u64 xv[8] = {x0.x, x0.y, x1.x, x1.y, x2.x, x2.y, x3.x, x3.y};
        #pragma unroll
        for (int o = 0; o < 8; o++)
            #pragma unroll
            for (int np = 0; np < 8; np++)
                FMA2(acc[o][np], ws[o], xv[np]);
    }

    int d = n0 >> 12;
    int sb = (n0 & 4095) + nt*16;
    float* gq = g_q + b*8388608 + ot*256 + d*8;
    #pragma unroll
    for (int np = 0; np < 8; np++) {
        float2 f[8];
        #pragma unroll
        for (int o = 0; o < 8; o++) f[o] = upk2(acc[o][np]);
        float* p0 = gq + (u64)(sb + 2*np)*2048;
        ((float4*)p0)[0] = make_float4(f[0].x, f[1].x, f[2].x, f[3].x);
        ((float4*)p0)[1] = make_float4(f[4].x, f[5].x, f[6].x, f[7].x);
        float* p1 = gq + (u64)(sb + 2*np + 1)*2048;
        ((float4*)p1)[0] = make_float4(f[0].y, f[1].y, f[2].y, f[3].y);
        ((float4*)p1)[1] = make_float4(f[4].y, f[5].y, f[6].y, f[7].y);
    }
}

// ---------------------------------------------------------------------------
// Kernel 2: fused K+V projection -> attention layout.
// Block [64o x 128n], 128 threads, thread tile [8o x 8n] x 2 matrices.
// ---------------------------------------------------------------------------
__global__ void __launch_bounds__(128) k_proj_kv(const float* __restrict__ x,
                                                 const float* __restrict__ Wk,
                                                 const float* __restrict__ Wv)
{
    __shared__ __align__(16) float xs[64*128];
    __shared__ __align__(16) float KA[2048], KB[2048];
    __shared__ __align__(16) float VA[2048], VB[2048];
    int b = blockIdx.x >> 10;
    int n0 = (blockIdx.x & 1023) << 7;
    stage_W2(KA, KB, Wk);
    stage_W2(VA, VB, Wv);
    {
        const float4* xg = (const float4*)(x + b*8388608 + n0);
        float4* xs4 = (float4*)xs;
        #pragma unroll
        for (int i = 0; i < 16; i++) {
            int idx = threadIdx.x + i*128;
            int c = idx >> 5, n4 = idx & 31;
            xs4[c*32 + n4] = xg[c*32768 + n4];
        }
    }
    __syncthreads();

    int ot = threadIdx.x & 7, nt = threadIdx.x >> 3;   // n = nt*8
    u64 ak[8][4], av[8][4];
    #pragma unroll
    for (int o = 0; o < 8; o++)
        #pragma unroll
        for (int np = 0; np < 4; np++) { ak[o][np] = 0ull; av[o][np] = 0ull; }

    #pragma unroll 2
    for (int k = 0; k < 64; k++) {
        float4 ka = *(const float4*)&KA[k*32 + ot*4];
        float4 kb = *(const float4*)&KB[k*32 + ot*4];
        float4 va = *(const float4*)&VA[k*32 + ot*4];
        float4 vb = *(const float4*)&VB[k*32 + ot*4];
        u64 wk[8] = {pk2(ka.x,ka.x), pk2(ka.y,ka.y), pk2(ka.z,ka.z), pk2(ka.w,ka.w),
                     pk2(kb.x,kb.x), pk2(kb.y,kb.y), pk2(kb.z,kb.z), pk2(kb.w,kb.w)};
        u64 wv[8] = {pk2(va.x,va.x), pk2(va.y,va.y), pk2(va.z,va.z), pk2(va.w,va.w),
                     pk2(vb.x,vb.x), pk2(vb.y,vb.y), pk2(vb.z,vb.z), pk2(vb.w,vb.w)};
        const ulonglong2* xp = (const ulonglong2*)&xs[k*128 + nt*8];
        ulonglong2 x0 = xp[0], x1 = xp[1];
        u64 xv[4] = {x0.x, x0.y, x1.x, x1.y};
        #pragma unroll
        for (int o = 0; o < 8; o++)
            #pragma unroll
            for (int np = 0; np < 4; np++) {
                FMA2(ak[o][np], wk[o], xv[np]);
                FMA2(av[o][np], wv[o], xv[np]);
            }
    }

    int d = n0 >> 12;
    int sb = (n0 & 4095) + nt*8;
    u64 boff = (u64)b*8388608 + ot*256 + d*8;
    #pragma unroll
    for (int np = 0; np < 4; np++) {
        float2 fk[8], fv[8];
        #pragma unroll
        for (int o = 0; o < 8; o++) { fk[o] = upk2(ak[o][np]); fv[o] = upk2(av[o][np]); }
        u64 s0 = (u64)(sb + 2*np)*2048, s1 = (u64)(sb + 2*np + 1)*2048;
        float* p;
        p = g_k + boff + s0;
        ((float4*)p)[0] = make_float4(fk[0].x, fk[1].x, fk[2].x, fk[3].x);
        ((float4*)p)[1] = make_float4(fk[4].x, fk[5].x, fk[6].x, fk[7].x);
        p = g_k + boff + s1;
        ((float4*)p)[0] = make_float4(fk[0].y, fk[1].y, fk[2].y, fk[3].y);
        ((float4*)p)[1] = make_float4(fk[4].y, fk[5].y, fk[6].y, fk[7].y);
        p = g_v + boff + s0;
        ((float4*)p)[0] = make_float4(fv[0].x, fv[1].x, fv[2].x, fv[3].x);
        ((float4*)p)[1] = make_float4(fv[4].x, fv[5].x, fv[6].x, fv[7].x);
        p = g_v + boff + s1;
        ((float4*)p)[0] = make_float4(fv[0].y, fv[1].y, fv[2].y, fv[3].y);
        ((float4*)p)[1] = make_float4(fv[4].y, fv[5].y, fv[6].y, fv[7].y);
    }
}

// ---------------------------------------------------------------------------
// Kernel 3: attention (unchanged from R3). Block = (b, head, 8 consecutive s);
// warp per s. Writes ctx to g_c in x-layout via shared transpose.
// ---------------------------------------------------------------------------
__global__ void __launch_bounds__(256) k_attn()
{
    __shared__ __align__(16) float ks[8][256];
    __shared__ __align__(16) float vsm[8][256];
    __shared__ __align__(16) float sctx[8*32*9];
    int warp = threadIdx.x >> 5, lane = threadIdx.x & 31;
    int blk = blockIdx.x;
    int s8   = blk & 511;
    int head = (blk >> 9) & 7;
    int b    = blk >> 12;
    int s = s8*8 + warp;
    int u = ((b << 12) + s)*8 + head;

    const float4* kp = (const float4*)(g_k + (u64)u*256);
    const float4* vp = (const float4*)(g_v + (u64)u*256);
    float4* ksw = (float4*)ks[warp];
    float4* vsw = (float4*)vsm[warp];
    ksw[lane*2]     = kp[lane*2];
    ksw[lane*2 + 1] = kp[lane*2 + 1];
    vsw[lane*2]     = vp[lane*2];
    vsw[lane*2 + 1] = vp[lane*2 + 1];

    const float4* qp = (const float4*)(g_q + (u64)u*256 + lane*8);
    float4 q0 = qp[0], q1 = qp[1];
    u64 qv0 = pk2(q0.x, q0.y), qv1 = pk2(q0.z, q0.w);
    u64 qv2 = pk2(q1.x, q1.y), qv3 = pk2(q1.z, q1.w);
    __syncwarp();

    float sim[32];
    #pragma unroll
    for (int j = 0; j < 32; j++) {
        const ulonglong2* kq = (const ulonglong2*)&ks[warp][j*8];
        ulonglong2 ka = kq[0], kb = kq[1];
        u64 a0 = 0ull, a1 = 0ull;
        FMA2(a0, ka.x, qv0); FMA2(a1, ka.y, qv1);
        FMA2(a0, kb.x, qv2); FMA2(a1, kb.y, qv3);
        float2 f0 = upk2(a0), f1 = upk2(a1);
        sim[j] = ((f0.x + f0.y) + (f1.x + f1.y)) * 0.35355339059327373f;
    }

    float m = sim[0];
    #pragma unroll
    for (int j = 1; j < 32; j++) m = fmaxf(m, sim[j]);

    float ssum = 0.f;
    u64 c0 = 0ull, c1 = 0ull, c2 = 0ull, c3 = 0ull;
    #pragma unroll
    for (int j = 0; j < 32; j++) {
        float p = __expf(sim[j] - m);
        ssum += p;
        u64 pp = pk2(p, p);
        const ulonglong2* vq = (const ulonglong2*)&vsm[warp][j*8];
        ulonglong2 va = vq[0], vb = vq[1];
        FMA2(c0, va.x, pp); FMA2(c1, va.y, pp);
        FMA2(c2, vb.x, pp); FMA2(c3, vb.y, pp);
    }

    float inv = 1.f / ssum;
    float2 r0 = upk2(c0), r1 = upk2(c1), r2 = upk2(c2), r3 = upk2(c3);
    float vals[8] = {r0.x*inv, r0.y*inv, r1.x*inv, r1.y*inv,
                     r2.x*inv, r2.y*inv, r3.x*inv, r3.y*inv};
    #pragma unroll
    for (int e = 0; e < 8; e++)
        sctx[e*288 + lane*9 + warp] = vals[e];
    __syncthreads();

    int e = threadIdx.x >> 5, d = threadIdx.x & 31;
    const float* sp = &sctx[e*288 + d*9];
    float4 f0 = make_float4(sp[0], sp[1], sp[2], sp[3]);
    float4 f1 = make_float4(sp[4], sp[5], sp[6], sp[7]);
    float* dst = g_c + (u64)b*8388608 + (head*8 + e)*131072 + d*4096 + s8*8;
    ((float4*)dst)[0] = f0;
    ((float4*)dst)[1] = f1;
}

// ---------------------------------------------------------------------------
// Kernel 4: O projection. Same GEMM as k_proj_q; reads g_c (x-layout),
// writes out in x-layout with contiguous STG.128 per channel.
// ---------------------------------------------------------------------------
__global__ void __launch_bounds__(128) k_proj_o(const float* __restrict__ W,
                                                float* __restrict__ out)
{
    __shared__ __align__(16) float xs[64*256];
    __shared__ __align__(16) float WA[2048];
    __shared__ __align__(16) float WB[2048];
    int b = blockIdx.x >> 9;
    int n0 = (blockIdx.x & 511) << 8;
    stage_W2(WA, WB, W);
    {
        const float4* xg = (const float4*)(g_c + (u64)b*8388608 + n0);
        float4* xs4 = (float4*)xs;
        #pragma unroll
        for (int i = 0; i < 32; i++) {
            int idx = threadIdx.x + i*128;
            int c = idx >> 6, n4 = idx & 63;
            xs4[c*64 + n4] = xg[c*32768 + n4];
        }
    }
    __syncthreads();

    int ot = threadIdx.x & 7, nt = threadIdx.x >> 3;
    u64 acc[8][8];
    #pragma unroll
    for (int o = 0; o < 8; o++)
        #pragma unroll
        for (int np = 0; np < 8; np++) acc[o][np] = 0ull;

    #pragma unroll 2
    for (int k = 0; k < 64; k++) {
        float4 wa = *(const float4*)&WA[k*32 + ot*4];
        float4 wb = *(const float4*)&WB[k*32 + ot*4];
        u64 ws[8] = {pk2(wa.x,wa.x), pk2(wa.y,wa.y), pk2(wa.z,wa.z), pk2(wa.w,wa.w),
                     pk2(wb.x,wb.x), pk2(wb.y,wb.y), pk2(wb.z,wb.z), pk2(wb.w,wb.w)};
        const ulonglong2* xp = (const ulonglong2*)&xs[k*256 + nt*16];
        ulonglong2 x0 = xp[0], x1 = xp[1], x2 = xp[2], x3 = xp[3];
        u64 xv[8] = {x0.x, x0.y, x1.x, x1.y, x2.x, x2.y, x3.x, x3.y};
        #pragma unroll
        for (int o = 0; o < 8; o++)
            #pragma unroll
            for (int np = 0; np < 8; np++)
                FMA2(acc[o][np], ws[o], xv[np]);
    }

    float* ob = out + (u64)b*8388608 + n0 + nt*16;
    #pragma unroll
    for (int o = 0; o < 8; o++) {
        float* oc = ob + (u64)(ot*8 + o)*131072;
        #pragma unroll
        for (int q = 0; q < 4; q++) {
            float2 a = upk2(acc[o][2*q]);
            float2 c = upk2(acc[o][2*q + 1]);
            ((float4*)oc)[q] = make_float4(a.x, a.y, c.x, c.y);
        }
    }
}

extern "C" void kernel_launch(void* const* d_in, const int* in_sizes, int n_in,
                              void* d_out, int out_size)
{
    const float* qf = (const float*)d_in[0];
    const float* kf = (const float*)d_in[1];
    const float* Wq = (const float*)d_in[2];
    const float* Wk = (const float*)d_in[3];
    const float* Wv = (const float*)d_in[4];
    const float* Wo = (const float*)d_in[5];
    float* out = (float*)d_out;

    k_proj_q <<<1024, 128>>>(qf, Wq);
    k_proj_kv<<<2048, 128>>>(kf, Wk, Wv);
    k_attn   <<<8192, 256>>>();
    k_proj_o <<<1024, 128>>>(Wo, out);
}

// round 6
// speedup vs baseline: 1.7852x; 1.0185x over previous
#include <cuda_runtime.h>

#define NEL 16777216   // B*C*D*H*W
typedef unsigned long long u64;

// Scratch. q/k/v in attention layout [b][s][head][d][e], ctx in x-layout [B][C][N].
__device__ __align__(16) float g_q[NEL];
__device__ __align__(16) float g_k[NEL];
__device__ __align__(16) float g_v[NEL];
__device__ __align__(16) float g_c[NEL];

__device__ __forceinline__ u64 pk2(float lo, float hi) {
    u64 r; asm("mov.b64 %0, {%1,%2};" : "=l"(r) : "f"(lo), "f"(hi)); return r;
}
__device__ __forceinline__ float2 upk2(u64 v) {
    float2 r; asm("mov.b64 {%0,%1}, %2;" : "=f"(r.x), "=f"(r.y) : "l"(v)); return r;
}
#define FMA2(d, a, b) asm("fma.rn.f32x2 %0, %1, %2, %0;" : "+l"(d) : "l"(a), "l"(b))

// ---------------------------------------------------------------------------
// W[64][64] ([o][k]) -> two conflict-free planes, 16B stride over ot.
// ---------------------------------------------------------------------------
__device__ __forceinline__ void stage_W2(float* A, float* B,
                                         const float* __restrict__ Wsrc) {
    for (int idx = threadIdx.x; idx < 2048; idx += 256) {
        int k = idx >> 5, t = idx & 31;
        int ot = t >> 2, j = t & 3;
        A[idx] = Wsrc[(ot*8 + j)*64 + k];
        B[idx] = Wsrc[(ot*8 + 4 + j)*64 + k];
    }
}

// Stage one 32-channel chunk of x[64][N] into xs[32][256].
__device__ __forceinline__ void stage_chunk(float* xs, const float* __restrict__ xsrc,
                                            int b, int n0, int kc) {
    const float4* xg = (const float4*)(xsrc + (u64)b*8388608 + n0);
    float4* xs4 = (float4*)xs;
    #pragma unroll
    for (int i = 0; i < 8; i++) {
        int idx = threadIdx.x + i*256;
        int c = idx >> 6, n4 = idx & 63;
        xs4[c*64 + n4] = xg[(u64)(kc*32 + c)*32768 + n4];
    }
}

// ---------------------------------------------------------------------------
// Generic projection -> attention layout [b][s][head][d][e].
// Block [64o x 256n], 256 threads, thread tile [8o x 8n], k-split 2x32.
// dst selected DEVICE-SIDE via `which` (device globals must not be passed
// from host code).
// ---------------------------------------------------------------------------
__global__ void __launch_bounds__(256, 2) k_proj(const float* __restrict__ x,
                                                 const float* __restrict__ W,
                                                 int which)
{
    __shared__ __align__(16) float xs[32*256];
    __shared__ __align__(16) float WA[2048];
    __shared__ __align__(16) float WB[2048];
    float* dst = (which == 0) ? g_q : (which == 1) ? g_k : g_v;
    int b = blockIdx.x >> 9;
    int n0 = (blockIdx.x & 511) << 8;
    stage_W2(WA, WB, W);

    int ot = threadIdx.x & 7, nt = threadIdx.x >> 3;   // n = nt*8
    u64 acc[8][4];
    #pragma unroll
    for (int o = 0; o < 8; o++)
        #pragma unroll
        for (int np = 0; np < 4; np++) acc[o][np] = 0ull;

    #pragma unroll 1
    for (int kc = 0; kc < 2; kc++) {
        __syncthreads();
        stage_chunk(xs, x, b, n0, kc);
        __syncthreads();
        #pragma unroll 4
        for (int k = 0; k < 32; k++) {
            int kg = kc*32 + k;
            float4 wa = *(const float4*)&WA[kg*32 + ot*4];
            float4 wb = *(const float4*)&WB[kg*32 + ot*4];
            u64 ws[8] = {pk2(wa.x,wa.x), pk2(wa.y,wa.y), pk2(wa.z,wa.z), pk2(wa.w,wa.w),
                         pk2(wb.x,wb.x), pk2(wb.y,wb.y), pk2(wb.z,wb.z), pk2(wb.w,wb.w)};
            const ulonglong2* xp = (const ulonglong2*)&xs[k*256 + nt*8];
            ulonglong2 x0 = xp[0], x1 = xp[1];
            u64 xv[4] = {x0.x, x0.y, x1.x, x1.y};
            #pragma unroll
            for (int o = 0; o < 8; o++)
                #pragma unroll
                for (int np = 0; np < 4; np++)
                    FMA2(acc[o][np], ws[o], xv[np]);
        }
    }

    int d = n0 >> 12;
    int sb = (n0 & 4095) + nt*8;
    float* gq = dst + (u64)b*8388608 + ot*256 + d*8;
    #pragma unroll
    for (int np = 0; np < 4; np++) {
        float2 f[8];
        #pragma unroll
        for (int o = 0; o < 8; o++) f[o] = upk2(acc[o][np]);
        float* p0 = gq + (u64)(sb + 2*np)*2048;
        ((float4*)p0)[0] = make_float4(f[0].x, f[1].x, f[2].x, f[3].x);
        ((float4*)p0)[1] = make_float4(f[4].x, f[5].x, f[6].x, f[7].x);
        float* p1 = gq + (u64)(sb + 2*np + 1)*2048;
        ((float4*)p1)[0] = make_float4(f[0].y, f[1].y, f[2].y, f[3].y);
        ((float4*)p1)[1] = make_float4(f[4].y, f[5].y, f[6].y, f[7].y);
    }
}

// ---------------------------------------------------------------------------
// Attention: one-pass softmax (no max-sub; |sim·scale| small), exp2 with
// folded scale, fused dot->exp->sum->V accumulate. Block=(b,head,8 s).
// ---------------------------------------------------------------------------
__global__ void __launch_bounds__(256) k_attn()
{
    __shared__ __align__(16) float ks[8][256];
    __shared__ __align__(16) float vsm[8][256];
    __shared__ __align__(16) float sctx[8*32*9];
    int warp = threadIdx.x >> 5, lane = threadIdx.x & 31;
    int blk = blockIdx.x;
    int s8   = blk & 511;
    int head = (blk >> 9) & 7;
    int b    = blk >> 12;
    int s = s8*8 + warp;
    int u = ((b << 12) + s)*8 + head;

    const float4* kp = (const float4*)(g_k + (u64)u*256);
    const float4* vp = (const float4*)(g_v + (u64)u*256);
    float4* ksw = (float4*)ks[warp];
    float4* vsw = (float4*)vsm[warp];
    ksw[lane*2]     = kp[lane*2];
    ksw[lane*2 + 1] = kp[lane*2 + 1];
    vsw[lane*2]     = vp[lane*2];
    vsw[lane*2 + 1] = vp[lane*2 + 1];

    const float4* qp = (const float4*)(g_q + (u64)u*256 + lane*8);
    float4 q0 = qp[0], q1 = qp[1];
    u64 qv0 = pk2(q0.x, q0.y), qv1 = pk2(q0.z, q0.w);
    u64 qv2 = pk2(q1.x, q1.y), qv3 = pk2(q1.z, q1.w);
    __syncwarp();

    const float CEXP = 0.35355339059327373f * 1.4426950408889634f;
    float ssA = 0.f, ssB = 0.f;
    u64 c0 = 0ull, c1 = 0ull, c2 = 0ull, c3 = 0ull;
    #pragma unroll
    for (int j = 0; j < 32; j++) {
        const ulonglong2* kq = (const ulonglong2*)&ks[warp][j*8];
        ulonglong2 ka = kq[0], kb = kq[1];
        u64 a0 = 0ull, a1 = 0ull;
        FMA2(a0, ka.x, qv0); FMA2(a1, ka.y, qv1);
        FMA2(a0, kb.x, qv2); FMA2(a1, kb.y, qv3);
        float2 f0 = upk2(a0), f1 = upk2(a1);
        float p = exp2f(((f0.x + f0.y) + (f1.x + f1.y)) * CEXP);
        if (j & 1) ssB += p; else ssA += p;
        u64 pp = pk2(p, p);
        const ulonglong2* vq = (const ulonglong2*)&vsm[warp][j*8];
        ulonglong2 va = vq[0], vb = vq[1];
        FMA2(c0, va.x, pp); FMA2(c1, va.y, pp);
        FMA2(c2, vb.x, pp); FMA2(c3, vb.y, pp);
    }

    float inv = 1.f / (ssA + ssB);
    float2 r0 = upk2(c0), r1 = upk2(c1), r2 = upk2(c2), r3 = upk2(c3);
    float vals[8] = {r0.x*inv, r0.y*inv, r1.x*inv, r1.y*inv,
                     r2.x*inv, r2.y*inv, r3.x*inv, r3.y*inv};
    #pragma unroll
    for (int e = 0; e < 8; e++)
        sctx[e*288 + lane*9 + warp] = vals[e];
    __syncthreads();

    int e = threadIdx.x >> 5, d = threadIdx.x & 31;
    const float* sp = &sctx[e*288 + d*9];
    float4 f0 = make_float4(sp[0], sp[1], sp[2], sp[3]);
    float4 f1 = make_float4(sp[4], sp[5], sp[6], sp[7]);
    float* dst = g_c + (u64)b*8388608 + (head*8 + e)*131072 + d*4096 + s8*8;
    ((float4*)dst)[0] = f0;
    ((float4*)dst)[1] = f1;
}

// ---------------------------------------------------------------------------
// O projection: same GEMM core, reads g_c (x-layout) device-side,
// contiguous stores to out.
// ---------------------------------------------------------------------------
__global__ void __launch_bounds__(256, 2) k_proj_o(const float* __restrict__ W,
                                                   float* __restrict__ out)
{
    __shared__ __align__(16) float xs[32*256];
    __shared__ __align__(16) float WA[2048];
    __shared__ __align__(16) float WB[2048];
    int b = blockIdx.x >> 9;
    int n0 = (blockIdx.x & 511) << 8;
    stage_W2(WA, WB, W);

    int ot = threadIdx.x & 7, nt = threadIdx.x >> 3;
    u64 acc[8][4];
    #pragma unroll
    for (int o = 0; o < 8; o++)
        #pragma unroll
        for (int np = 0; np < 4; np++) acc[o][np] = 0ull;

    #pragma unroll 1
    for (int kc = 0; kc < 2; kc++) {
        __syncthreads();
        stage_chunk(xs, g_c, b, n0, kc);
        __syncthreads();
        #pragma unroll 4
        for (int k = 0; k < 32; k++) {
            int kg = kc*32 + k;
            float4 wa = *(const float4*)&WA[kg*32 + ot*4];
            float4 wb = *(const float4*)&WB[kg*32 + ot*4];
            u64 ws[8] = {pk2(wa.x,wa.x), pk2(wa.y,wa.y), pk2(wa.z,wa.z), pk2(wa.w,wa.w),
                         pk2(wb.x,wb.x), pk2(wb.y,wb.y), pk2(wb.z,wb.z), pk2(wb.w,wb.w)};
            const ulonglong2* xp = (const ulonglong2*)&xs[k*256 + nt*8];
            ulonglong2 x0 = xp[0], x1 = xp[1];
            u64 xv[4] = {x0.x, x0.y, x1.x, x1.y};
            #pragma unroll
            for (int o = 0; o < 8; o++)
                #pragma unroll
                for (int np = 0; np < 4; np++)
                    FMA2(acc[o][np], ws[o], xv[np]);
        }
    }

    float* ob = out + (u64)b*8388608 + n0 + nt*8;
    #pragma unroll
    for (int o = 0; o < 8; o++) {
        float* oc = ob + (u64)(ot*8 + o)*131072;
        float2 a0 = upk2(acc[o][0]), a1 = upk2(acc[o][1]);
        float2 a2 = upk2(acc[o][2]), a3 = upk2(acc[o][3]);
        ((float4*)oc)[0] = make_float4(a0.x, a0.y, a1.x, a1.y);
        ((float4*)oc)[1] = make_float4(a2.x, a2.y, a3.x, a3.y);
    }
}

extern "C" void kernel_launch(void* const* d_in, const int* in_sizes, int n_in,
                              void* d_out, int out_size)
{
    const float* qf = (const float*)d_in[0];
    const float* kf = (const float*)d_in[1];
    const float* Wq = (const float*)d_in[2];
    const float* Wk = (const float*)d_in[3];
    const float* Wv = (const float*)d_in[4];
    const float* Wo = (const float*)d_in[5];
    float* out = (float*)d_out;

    k_proj  <<<1024, 256>>>(qf, Wq, 0);
    k_proj  <<<1024, 256>>>(kf, Wk, 1);
    k_proj  <<<1024, 256>>>(kf, Wv, 2);
    k_attn  <<<8192, 256>>>();
    k_proj_o<<<1024, 256>>>(Wo, out);
}

// round 7
// speedup vs baseline: 1.7917x; 1.0036x over previous
#include <cuda_runtime.h>

#define NEL 16777216   // B*C*D*H*W
typedef unsigned long long u64;

// Scratch. q/k/v in attention layout [b][s][head][d][e], ctx in x-layout [B][C][N].
__device__ __align__(16) float g_q[NEL];
__device__ __align__(16) float g_k[NEL];
__device__ __align__(16) float g_v[NEL];
__device__ __align__(16) float g_c[NEL];

__device__ __forceinline__ u64 pk2(float lo, float hi) {
    u64 r; asm("mov.b64 %0, {%1,%2};" : "=l"(r) : "f"(lo), "f"(hi)); return r;
}
__device__ __forceinline__ float2 upk2(u64 v) {
    float2 r; asm("mov.b64 {%0,%1}, %2;" : "=f"(r.x), "=f"(r.y) : "l"(v)); return r;
}
#define FMA2(d, a, b) asm("fma.rn.f32x2 %0, %1, %2, %0;" : "+l"(d) : "l"(a), "l"(b))

// ---------------------------------------------------------------------------
// W[64][64] ([o][k]) -> two conflict-free planes, 16B stride over ot.
// ---------------------------------------------------------------------------
__device__ __forceinline__ void stage_W2(float* A, float* B,
                                         const float* __restrict__ Wsrc) {
    for (int idx = threadIdx.x; idx < 2048; idx += 256) {
        int k = idx >> 5, t = idx & 31;
        int ot = t >> 2, j = t & 3;
        A[idx] = Wsrc[(ot*8 + j)*64 + k];
        B[idx] = Wsrc[(ot*8 + 4 + j)*64 + k];
    }
}

// Stage one 32-channel chunk of x[64][N] into xs[32][256].
__device__ __forceinline__ void stage_chunk(float* xs, const float* __restrict__ xsrc,
                                            int b, int n0, int kc) {
    const float4* xg = (const float4*)(xsrc + (u64)b*8388608 + n0);
    float4* xs4 = (float4*)xs;
    #pragma unroll
    for (int i = 0; i < 8; i++) {
        int idx = threadIdx.x + i*256;
        int c = idx >> 6, n4 = idx & 63;
        xs4[c*64 + n4] = xg[(u64)(kc*32 + c)*32768 + n4];
    }
}

// ---------------------------------------------------------------------------
// Generic projection -> attention layout [b][s][head][d][e].
// Block [64o x 256n], 256 threads, thread tile [8o x 8n], k-split 2x32.
// dst selected DEVICE-SIDE via `which` (device globals must not be passed
// from host code).
// ---------------------------------------------------------------------------
__global__ void __launch_bounds__(256, 2) k_proj(const float* __restrict__ x,
                                                 const float* __restrict__ W,
                                                 int which)
{
    __shared__ __align__(16) float xs[32*256];
    __shared__ __align__(16) float WA[2048];
    __shared__ __align__(16) float WB[2048];
    float* dst = (which == 0) ? g_q : (which == 1) ? g_k : g_v;
    int b = blockIdx.x >> 9;
    int n0 = (blockIdx.x & 511) << 8;
    stage_W2(WA, WB, W);

    int ot = threadIdx.x & 7, nt = threadIdx.x >> 3;   // n = nt*8
    u64 acc[8][4];
    #pragma unroll
    for (int o = 0; o < 8; o++)
        #pragma unroll
        for (int np = 0; np < 4; np++) acc[o][np] = 0ull;

    #pragma unroll 1
    for (int kc = 0; kc < 2; kc++) {
        __syncthreads();
        stage_chunk(xs, x, b, n0, kc);
        __syncthreads();
        #pragma unroll 4
        for (int k = 0; k < 32; k++) {
            int kg = kc*32 + k;
            float4 wa = *(const float4*)&WA[kg*32 + ot*4];
            float4 wb = *(const float4*)&WB[kg*32 + ot*4];
            u64 ws[8] = {pk2(wa.x,wa.x), pk2(wa.y,wa.y), pk2(wa.z,wa.z), pk2(wa.w,wa.w),
                         pk2(wb.x,wb.x), pk2(wb.y,wb.y), pk2(wb.z,wb.z), pk2(wb.w,wb.w)};
            const ulonglong2* xp = (const ulonglong2*)&xs[k*256 + nt*8];
            ulonglong2 x0 = xp[0], x1 = xp[1];
            u64 xv[4] = {x0.x, x0.y, x1.x, x1.y};
            #pragma unroll
            for (int o = 0; o < 8; o++)
                #pragma unroll
                for (int np = 0; np < 4; np++)
                    FMA2(acc[o][np], ws[o], xv[np]);
        }
    }

    int d = n0 >> 12;
    int sb = (n0 & 4095) + nt*8;
    float* gq = dst + (u64)b*8388608 + ot*256 + d*8;
    #pragma unroll
    for (int np = 0; np < 4; np++) {
        float2 f[8];
        #pragma unroll
        for (int o = 0; o < 8; o++) f[o] = upk2(acc[o][np]);
        float* p0 = gq + (u64)(sb + 2*np)*2048;
        ((float4*)p0)[0] = make_float4(f[0].x, f[1].x, f[2].x, f[3].x);
        ((float4*)p0)[1] = make_float4(f[4].x, f[5].x, f[6].x, f[7].x);
        float* p1 = gq + (u64)(sb + 2*np + 1)*2048;
        ((float4*)p1)[0] = make_float4(f[0].y, f[1].y, f[2].y, f[3].y);
        ((float4*)p1)[1] = make_float4(f[4].y, f[5].y, f[6].y, f[7].y);
    }
}

// ---------------------------------------------------------------------------
// Attention: one-pass softmax (no max-sub; |sim·scale| small), exp2 with
// folded scale, fused dot->exp->sum->V accumulate. Block=(b,head,8 s).
// ---------------------------------------------------------------------------
__global__ void __launch_bounds__(256) k_attn()
{
    __shared__ __align__(16) float ks[8][256];
    __shared__ __align__(16) float vsm[8][256];
    __shared__ __align__(16) float sctx[8*32*9];
    int warp = threadIdx.x >> 5, lane = threadIdx.x & 31;
    int blk = blockIdx.x;
    int s8   = blk & 511;
    int head = (blk >> 9) & 7;
    int b    = blk >> 12;
    int s = s8*8 + warp;
    int u = ((b << 12) + s)*8 + head;

    const float4* kp = (const float4*)(g_k + (u64)u*256);
    const float4* vp = (const float4*)(g_v + (u64)u*256);
    float4* ksw = (float4*)ks[warp];
    float4* vsw = (float4*)vsm[warp];
    ksw[lane*2]     = kp[lane*2];
    ksw[lane*2 + 1] = kp[lane*2 + 1];
    vsw[lane*2]     = vp[lane*2];
    vsw[lane*2 + 1] = vp[lane*2 + 1];

    const float4* qp = (const float4*)(g_q + (u64)u*256 + lane*8);
    float4 q0 = qp[0], q1 = qp[1];
    u64 qv0 = pk2(q0.x, q0.y), qv1 = pk2(q0.z, q0.w);
    u64 qv2 = pk2(q1.x, q1.y), qv3 = pk2(q1.z, q1.w);
    __syncwarp();

    const float CEXP = 0.35355339059327373f * 1.4426950408889634f;
    float ssA = 0.f, ssB = 0.f;
    u64 c0 = 0ull, c1 = 0ull, c2 = 0ull, c3 = 0ull;
    #pragma unroll
    for (int j = 0; j < 32; j++) {
        const ulonglong2* kq = (const ulonglong2*)&ks[warp][j*8];
        ulonglong2 ka = kq[0], kb = kq[1];
        u64 a0 = 0ull, a1 = 0ull;
        FMA2(a0, ka.x, qv0); FMA2(a1, ka.y, qv1);
        FMA2(a0, kb.x, qv2); FMA2(a1, kb.y, qv3);
        float2 f0 = upk2(a0), f1 = upk2(a1);
        float p = exp2f(((f0.x + f0.y) + (f1.x + f1.y)) * CEXP);
        if (j & 1) ssB += p; else ssA += p;
        u64 pp = pk2(p, p);
        const ulonglong2* vq = (const ulonglong2*)&vsm[warp][j*8];
        ulonglong2 va = vq[0], vb = vq[1];
        FMA2(c0, va.x, pp); FMA2(c1, va.y, pp);
        FMA2(c2, vb.x, pp); FMA2(c3, vb.y, pp);
    }

    float inv = 1.f / (ssA + ssB);
    float2 r0 = upk2(c0), r1 = upk2(c1), r2 = upk2(c2), r3 = upk2(c3);
    float vals[8] = {r0.x*inv, r0.y*inv, r1.x*inv, r1.y*inv,
                     r2.x*inv, r2.y*inv, r3.x*inv, r3.y*inv};
    #pragma unroll
    for (int e = 0; e < 8; e++)
        sctx[e*288 + lane*9 + warp] = vals[e];
    __syncthreads();

    int e = threadIdx.x >> 5, d = threadIdx.x & 31;
    const float* sp = &sctx[e*288 + d*9];
    float4 f0 = make_float4(sp[0], sp[1], sp[2], sp[3]);
    float4 f1 = make_float4(sp[4], sp[5], sp[6], sp[7]);
    float* dst = g_c + (u64)b*8388608 + (head*8 + e)*131072 + d*4096 + s8*8;
    ((float4*)dst)[0] = f0;
    ((float4*)dst)[1] = f1;
}

// ---------------------------------------------------------------------------
// O projection: same GEMM core, reads g_c (x-layout) device-side,
// contiguous stores to out.
// ---------------------------------------------------------------------------
__global__ void __launch_bounds__(256, 2) k_proj_o(const float* __restrict__ W,
                                                   float* __restrict__ out)
{
    __shared__ __align__(16) float xs[32*256];
    __shared__ __align__(16) float WA[2048];
    __shared__ __align__(16) float WB[2048];
    int b = blockIdx.x >> 9;
    int n0 = (blockIdx.x & 511) << 8;
    stage_W2(WA, WB, W);

    int ot = threadIdx.x & 7, nt = threadIdx.x >> 3;
    u64 acc[8][4];
    #pragma unroll
    for (int o = 0; o < 8; o++)
        #pragma unroll
        for (int np = 0; np < 4; np++) acc[o][np] = 0ull;

    #pragma unroll 1
    for (int kc = 0; kc < 2; kc++) {
        __syncthreads();
        stage_chunk(xs, g_c, b, n0, kc);
        __syncthreads();
        #pragma unroll 4
        for (int k = 0; k < 32; k++) {
            int kg = kc*32 + k;
            float4 wa = *(const float4*)&WA[kg*32 + ot*4];
            float4 wb = *(const float4*)&WB[kg*32 + ot*4];
            u64 ws[8] = {pk2(wa.x,wa.x), pk2(wa.y,wa.y), pk2(wa.z,wa.z), pk2(wa.w,wa.w),
                         pk2(wb.x,wb.x), pk2(wb.y,wb.y), pk2(wb.z,wb.z), pk2(wb.w,wb.w)};
            const ulonglong2* xp = (const ulonglong2*)&xs[k*256 + nt*8];
            ulonglong2 x0 = xp[0], x1 = xp[1];
            u64 xv[4] = {x0.x, x0.y, x1.x, x1.y};
            #pragma unroll
            for (int o = 0; o < 8; o++)
                #pragma unroll
                for (int np = 0; np < 4; np++)
                    FMA2(acc[o][np], ws[o], xv[np]);
        }
    }

    float* ob = out + (u64)b*8388608 + n0 + nt*8;
    #pragma unroll
    for (int o = 0; o < 8; o++) {
        float* oc = ob + (u64)(ot*8 + o)*131072;
        float2 a0 = upk2(acc[o][0]), a1 = upk2(acc[o][1]);
        float2 a2 = upk2(acc[o][2]), a3 = upk2(acc[o][3]);
        ((float4*)oc)[0] = make_float4(a0.x, a0.y, a1.x, a1.y);
        ((float4*)oc)[1] = make_float4(a2.x, a2.y, a3.x, a3.y);
    }
}

extern "C" void kernel_launch(void* const* d_in, const int* in_sizes, int n_in,
                              void* d_out, int out_size)
{
    const float* qf = (const float*)d_in[0];
    const float* kf = (const float*)d_in[1];
    const float* Wq = (const float*)d_in[2];
    const float* Wk = (const float*)d_in[3];
    const float* Wv = (const float*)d_in[4];
    const float* Wo = (const float*)d_in[5];
    float* out = (float*)d_out;

    k_proj  <<<1024, 256>>>(qf, Wq, 0);
    k_proj  <<<1024, 256>>>(kf, Wk, 1);
    k_proj  <<<1024, 256>>>(kf, Wv, 2);
    k_attn  <<<8192, 256>>>();
    k_proj_o<<<1024, 256>>>(Wo, out);
}